// round 9
// baseline (speedup 1.0000x reference)
#include <cuda_runtime.h>
#include <cuda_bf16.h>
#include <cstdint>

// Problem dims
#define NB  16
#define CCH 256
#define TT  256
#define VV  25
#define VPN 20
#define SS  3
#define ICN 64
#define CT   (CCH*TT)      // 65536
#define NCOL (TT*VPN)      // 5120
#define M1 384
#define KK1 256
#define M2 256
#define KK2 768

// ---------------- scratch (device globals; no runtime allocation) -------------
__device__ float g_xp[(size_t)NB*CT*VPN];
__device__ float g_fab[(size_t)NB*M1*NCOL];
__device__ float g_spart[16*48*400];
__device__ float g_att[48*400];
__device__ float g_z[(size_t)NB*SS*CT*VPN];
__device__ float g_y[(size_t)NB*CCH*NCOL];
__device__ float g_bn[2*CCH];
// pre-split bf16 weight images, laid out exactly as the smem tiles:
// per chunk: [split hi|lo][128 rows][40 bf16 (32 k + 8 pad)]  = 10240 elems
__device__ __nv_bfloat16 g_w0[3*8*10240];    // GEMM0: 3 rowTiles x 8 chunks
__device__ __nv_bfloat16 g_w1[2*24*10240];   // GEMM1: 2 rowTiles x 24 chunks

// ---------------- weight prep: fp32 -> split bf16 images -----------------------
__global__ void prep_w0(const float* __restrict__ wa, const float* __restrict__ wb) {
    int r = blockIdx.x;          // 0..383
    int k = threadIdx.x;         // 0..255
    float v = (r < 192) ? wa[r*256 + k] : wb[(r-192)*256 + k];
    __nv_bfloat16 h = __float2bfloat16(v);
    __nv_bfloat16 l = __float2bfloat16(v - __bfloat162float(h));
    int rowTile = r >> 7, m = r & 127, ch = k >> 5, kk = k & 31;
    size_t base = (size_t)(rowTile*8 + ch) * 10240;
    g_w0[base +        m*40 + kk] = h;
    g_w0[base + 5120 + m*40 + kk] = l;
}
__global__ void prep_w1(const float* __restrict__ wd) {
    int r = blockIdx.x;          // 0..255 (output channel o)
    int k = threadIdx.x;         // 0..767 (s*256 + c)
    float v = wd[(k >> 8)*65536 + r*256 + (k & 255)];
    __nv_bfloat16 h = __float2bfloat16(v);
    __nv_bfloat16 l = __float2bfloat16(v - __bfloat162float(h));
    int rowTile = r >> 7, m = r & 127, ch = k >> 5, kk = k & 31;
    size_t base = (size_t)(rowTile*24 + ch) * 10240;
    g_w1[base +        m*40 + kk] = h;
    g_w1[base + 5120 + m*40 + kk] = l;
}

// ---------------- K1: xp = einsum('nctv,vu->nctu', x, w_e) + b_e --------------
__global__ void __launch_bounds__(256) k1_xp(const float* __restrict__ x,
                                             const float* __restrict__ w_e,
                                             const float* __restrict__ b_e) {
    __shared__ float sw[VV*VPN];
    __shared__ float sb[VPN];
    int tid = threadIdx.x;
    for (int i = tid; i < VV*VPN; i += 256) sw[i] = w_e[i];
    if (tid < VPN) sb[tid] = b_e[tid];
    __syncthreads();
    size_t row0 = ((size_t)blockIdx.x * 256 + tid) * 2;
    float xr[2][VV];
    #pragma unroll
    for (int r = 0; r < 2; r++) {
        const float* xr0 = x + (row0 + r) * VV;
        #pragma unroll
        for (int v = 0; v < VV; v++) xr[r][v] = xr0[v];
    }
    float acc[2][VPN];
    #pragma unroll
    for (int u = 0; u < VPN; u++) { float b = sb[u]; acc[0][u] = b; acc[1][u] = b; }
    #pragma unroll
    for (int v = 0; v < VV; v++) {
        float x0 = xr[0][v], x1 = xr[1][v];
        #pragma unroll
        for (int u = 0; u < VPN; u++) {
            float w = sw[v*VPN + u];
            acc[0][u] += x0 * w;
            acc[1][u] += x1 * w;
        }
    }
    #pragma unroll
    for (int r = 0; r < 2; r++) {
        float* o = &g_xp[(row0 + r) * VPN];
        #pragma unroll
        for (int q = 0; q < 5; q++)
            *(float4*)(o + q*4) = make_float4(acc[r][q*4], acc[r][q*4+1], acc[r][q*4+2], acc[r][q*4+3]);
    }
}

// ---------------- HMMA GEMM: mma.sync m16n8k16 bf16 + ldmatrix -----------------
__device__ __forceinline__ void mma_bf16(float* c, const uint32_t* a, const uint32_t* b) {
    asm volatile(
        "mma.sync.aligned.m16n8k16.row.col.f32.bf16.bf16.f32 "
        "{%0,%1,%2,%3}, {%4,%5,%6,%7}, {%8,%9}, {%0,%1,%2,%3};"
        : "+f"(c[0]), "+f"(c[1]), "+f"(c[2]), "+f"(c[3])
        : "r"(a[0]), "r"(a[1]), "r"(a[2]), "r"(a[3]), "r"(b[0]), "r"(b[1]));
}
__device__ __forceinline__ void ldsm_x4(uint32_t* r, uint32_t addr) {
    asm volatile("ldmatrix.sync.aligned.m8n8.x4.shared.b16 {%0,%1,%2,%3}, [%4];"
        : "=r"(r[0]), "=r"(r[1]), "=r"(r[2]), "=r"(r[3]) : "r"(addr));
}
__device__ __forceinline__ uint32_t smem_u32(const void* p) {
    uint32_t a; asm("{ .reg .u64 t; cvta.to.shared.u64 t, %1; cvt.u32.u64 %0, t; }" : "=r"(a) : "l"(p));
    return a;
}

template<int MODE>
__global__ void __launch_bounds__(256) gemm_mma(const float* __restrict__ bias0,
                                                const float* __restrict__ bias1) {
    constexpr int NCH = MODE ? 24 : 8;
    // [split hi|lo][128 rows][40 bf16]; split stride = 5120 elems = 10240 BYTES
    __shared__ __align__(16) __nv_bfloat16 sA[2][128][40];
    __shared__ __align__(16) __nv_bfloat16 sB[2][128][40];

    const __nv_bfloat16* img = MODE ? g_w1 : g_w0;
    const float* act = MODE ? g_z : g_xp;

    int tid = threadIdx.x, lane = tid & 31, wid = tid >> 5;
    int g = lane >> 2, t = lane & 3;
    int col0 = blockIdx.x * 128;
    int rowTile = blockIdx.y;
    int n = blockIdx.z;
    size_t actBase = (size_t)n * (MODE ? 3932160 : 1310720) + col0;
    int Mw = (wid & 3) * 32, Nw = (wid >> 2) * 64;

    // ldmatrix per-thread tile-terms (bf16-element units)
    int q = lane >> 3, rr = lane & 7;
    int aTerm = ((q & 1)*8 + rr)*40 + (q >> 1)*8;   // A: m0=(rb0,klo) m1=(rb1,klo) m2=(rb0,khi) m3=(rb1,khi)
    int bTerm = ((q >> 1)*8 + rr)*40 + (q & 1)*8;   // B: m0=(n0,klo) m1=(n0,khi) m2=(n0+8,klo) m3=(n0+8,khi)
    uint32_t sA_u = smem_u32(&sA[0][0][0]);
    uint32_t sB_u = smem_u32(&sB[0][0][0]);

    float acc[2][8][4];
    #pragma unroll
    for (int i = 0; i < 2; i++)
        #pragma unroll
        for (int j = 0; j < 8; j++)
            #pragma unroll
            for (int qq = 0; qq < 4; qq++) acc[i][j][qq] = 0.f;

    const __nv_bfloat16* wimg = img + (size_t)(rowTile * NCH) * 10240;
    int cS = tid & 127, kbS = tid >> 7;

    for (int ch = 0; ch < NCH; ch++) {
        __syncthreads();
        // stage weights (flat copy of pre-built image)
        {
            const uint4* src = (const uint4*)(wimg + (size_t)ch * 10240);
            uint4* dst = (uint4*)&sA[0][0][0];
            #pragma unroll
            for (int i = 0; i < 5; i++) dst[tid + i*256] = src[tid + i*256];
        }
        // stage activations: fp32 -> split bf16, transposed to [col][k]
        {
            const float* ap = act + actBase + (size_t)(ch*32) * 5120;
            #pragma unroll
            for (int i = 0; i < 16; i++) {
                int kk = kbS + i*2;
                float f = ap[(size_t)kk * 5120 + cS];
                __nv_bfloat16 h = __float2bfloat16(f);
                __nv_bfloat16 l = __float2bfloat16(f - __bfloat162float(h));
                sB[0][cS][kk] = h;
                sB[1][cS][kk] = l;
            }
        }
        __syncthreads();
        #pragma unroll
        for (int k0 = 0; k0 < 32; k0 += 16) {
            uint32_t ah[2][4], al[2][4], bh[8][2], bl[8][2];
            #pragma unroll
            for (int mf = 0; mf < 2; mf++) {
                uint32_t base = (uint32_t)(((Mw + mf*16)*40 + k0 + aTerm) * 2);
                ldsm_x4(ah[mf], sA_u + base);
                ldsm_x4(al[mf], sA_u + base + 10240u);     // FIX: lo split = +10240 BYTES
            }
            #pragma unroll
            for (int pf = 0; pf < 4; pf++) {
                uint32_t base = (uint32_t)(((Nw + pf*16)*40 + k0 + bTerm) * 2);
                ldsm_x4(&bh[2*pf][0], sB_u + base);
                ldsm_x4(&bl[2*pf][0], sB_u + base + 10240u); // FIX: lo split = +10240 BYTES
            }
            #pragma unroll
            for (int mf = 0; mf < 2; mf++)
                #pragma unroll
                for (int nf = 0; nf < 8; nf++) {
                    mma_bf16(acc[mf][nf], ah[mf], bh[nf]);   // hi*hi
                    mma_bf16(acc[mf][nf], ah[mf], bl[nf]);   // hi*lo
                    mma_bf16(acc[mf][nf], al[mf], bh[nf]);   // lo*hi
                }
        }
    }

    // epilogue: direct global stores (+bias), float2 per c-pair
    float* outb = (MODE ? g_y : g_fab) + (size_t)n * (MODE ? 1310720 : 1966080);
    #pragma unroll
    for (int mf = 0; mf < 2; mf++) {
        int r = rowTile*128 + Mw + mf*16 + g;
        float bv0, bv1;
        if (MODE) {
            bv0 = bias0[r]   + bias0[256 + r]   + bias0[512 + r];
            bv1 = bias0[r+8] + bias0[256 + r+8] + bias0[512 + r+8];
        } else {
            bv0 = (r   < 192) ? bias0[r]   : bias1[r   - 192];
            bv1 = (r+8 < 192) ? bias0[r+8] : bias1[r+8 - 192];
        }
        #pragma unroll
        for (int nf = 0; nf < 8; nf++) {
            int col = col0 + Nw + nf*8 + 2*t;
            float* o = outb + (size_t)r * 5120 + col;
            *(float2*)o              = make_float2(acc[mf][nf][0] + bv0, acc[mf][nf][1] + bv0);
            *(float2*)(o + 8*5120)   = make_float2(acc[mf][nf][2] + bv1, acc[mf][nf][3] + bv1);
        }
    }
}

// ---------------- K3: scores partials ------------------------------------------
__global__ void __launch_bounds__(512) k3_scores() {
    __shared__ float sfa[8][320];
    __shared__ float sfb[8][320];
    int tid = threadIdx.x;
    int tc = blockIdx.x;
    int ns = blockIdx.y;
    int n = ns / 3, s = ns % 3;
    const float* faB = g_fab + (size_t)n*M1*NCOL + (size_t)(s*64)*NCOL + tc*320;
    const float* fbB = faB + (size_t)192*NCOL;
    float acc = 0.f;
    int v = tid / 20, u = tid % 20;
    for (int ib = 0; ib < 64; ib += 8) {
        for (int idx = tid; idx < 2560; idx += 512) {
            int ii = idx / 320, jj = idx % 320;
            sfa[ii][jj] = faB[(size_t)(ib+ii)*NCOL + jj];
            sfb[ii][jj] = fbB[(size_t)(ib+ii)*NCOL + jj];
        }
        __syncthreads();
        if (tid < 400) {
            #pragma unroll
            for (int ii = 0; ii < 8; ii++)
                #pragma unroll
                for (int t2 = 0; t2 < 16; t2++)
                    acc += sfa[ii][t2*20 + v] * sfb[ii][t2*20 + u];
        }
        __syncthreads();
    }
    if (tid < 400)
        g_spart[(tc*48 + ns)*400 + tid] = acc * (1.0f/16384.0f);
}

// ---------------- K4: reduce + softmax over v + (A_fix+PA) ---------------------
__global__ void __launch_bounds__(512) k4_softmax(const float* __restrict__ PA,
                                                  const float* __restrict__ A_fix) {
    __shared__ float ssc[400];
    int tid = threadIdx.x;
    int ns = blockIdx.x;
    int s = ns % 3;
    if (tid < 400) {
        float a = 0.f;
        #pragma unroll
        for (int tc = 0; tc < 16; tc++) a += g_spart[(tc*48 + ns)*400 + tid];
        ssc[tid] = a;
    }
    __syncthreads();
    if (tid < 20) {
        int u = tid;
        float mx = -1e30f;
        #pragma unroll
        for (int v = 0; v < 20; v++) mx = fmaxf(mx, ssc[v*20 + u]);
        float e[20];
        float sum = 0.f;
        #pragma unroll
        for (int v = 0; v < 20; v++) { e[v] = expf(ssc[v*20 + u] - mx); sum += e[v]; }
        float inv = 1.0f / sum;
        #pragma unroll
        for (int v = 0; v < 20; v++) {
            int ai = (s*20 + v)*20 + u;
            g_att[ns*400 + v*20 + u] = e[v]*inv + A_fix[ai] + PA[ai];
        }
    }
}

// ---------------- K5: z for all 3 subsets from one xp read ---------------------
__global__ void __launch_bounds__(256) k5_z() {
    __shared__ float satt[3*400];
    int tid = threadIdx.x;
    int n = blockIdx.y;
    for (int i = tid; i < 3*400; i += 256) satt[i] = g_att[n*1200 + i];
    __syncthreads();
    size_t row = (size_t)blockIdx.x * 256 + tid;
    const float* xr0 = &g_xp[((size_t)n*CT + row)*VPN];
    float xr[20];
    #pragma unroll
    for (int q = 0; q < 5; q++)
        *(float4*)&xr[q*4] = *(const float4*)(xr0 + q*4);
    #pragma unroll
    for (int s = 0; s < 3; s++) {
        float acc[20];
        #pragma unroll
        for (int u = 0; u < 20; u++) acc[u] = 0.f;
        #pragma unroll
        for (int v = 0; v < 20; v++) {
            float x0 = xr[v];
            #pragma unroll
            for (int u = 0; u < 20; u++)
                acc[u] += x0 * satt[s*400 + v*20 + u];
        }
        float* zp = &g_z[(((size_t)n*3 + s)*CT + row)*VPN];
        #pragma unroll
        for (int q = 0; q < 5; q++)
            *(float4*)(zp + q*4) = make_float4(acc[q*4], acc[q*4+1], acc[q*4+2], acc[q*4+3]);
    }
}

// ---------------- K7: BN statistics ---------------------------------------------
__global__ void __launch_bounds__(256) k7_bn() {
    __shared__ double ssum[256];
    __shared__ double ssq[256];
    int o = blockIdx.x, tid = threadIdx.x;
    double s = 0.0, q = 0.0;
    for (int n = 0; n < NB; n++) {
        const float* yp = &g_y[((size_t)n*CCH + o)*NCOL];
        for (int j = tid; j < NCOL; j += 256) { double v = yp[j]; s += v; q += v*v; }
    }
    ssum[tid] = s; ssq[tid] = q;
    __syncthreads();
    for (int st = 128; st > 0; st >>= 1) {
        if (tid < st) { ssum[tid] += ssum[tid+st]; ssq[tid] += ssq[tid+st]; }
        __syncthreads();
    }
    if (tid == 0) {
        double cnt  = (double)NB * NCOL;
        double mean = ssum[0] / cnt;
        double var  = ssq[0] / cnt - mean*mean;
        g_bn[o]       = (float)mean;
        g_bn[256 + o] = (float)(1.0 / sqrt(var + 1e-5));
    }
}

// ---------------- K8: out = relu(BN(y)*gamma+beta + xp) -------------------------
__global__ void __launch_bounds__(256) k8_final(const float* __restrict__ gamma,
                                                const float* __restrict__ beta,
                                                float* __restrict__ out) {
    size_t idx = ((size_t)blockIdx.x * 256 + threadIdx.x) * 4;
    int o = (int)((idx / NCOL) % CCH);
    float rstd = g_bn[256 + o];
    float g = gamma[o] * rstd;
    float b = beta[o] - g_bn[o] * g;
    float4 y  = *(const float4*)&g_y[idx];
    float4 xp = *(const float4*)&g_xp[idx];
    float4 r;
    r.x = fmaxf(y.x*g + b + xp.x, 0.f);
    r.y = fmaxf(y.y*g + b + xp.y, 0.f);
    r.z = fmaxf(y.z*g + b + xp.z, 0.f);
    r.w = fmaxf(y.w*g + b + xp.w, 0.f);
    *(float4*)&out[idx] = r;
}

// ---------------- launch ---------------------------------------------------------
extern "C" void kernel_launch(void* const* d_in, const int* in_sizes, int n_in,
                              void* d_out, int out_size) {
    const float* x     = (const float*)d_in[0];
    const float* PA    = (const float*)d_in[1];
    const float* A_fix = (const float*)d_in[2];
    const float* w_e   = (const float*)d_in[3];
    const float* b_e   = (const float*)d_in[4];
    const float* wa    = (const float*)d_in[5];
    const float* ba    = (const float*)d_in[6];
    const float* wb    = (const float*)d_in[7];
    const float* bb    = (const float*)d_in[8];
    const float* wd    = (const float*)d_in[9];
    const float* bd    = (const float*)d_in[10];
    const float* gamma = (const float*)d_in[11];
    const float* beta  = (const float*)d_in[12];
    float* out = (float*)d_out;

    prep_w0<<<384, 256>>>(wa, wb);
    prep_w1<<<256, 768>>>(wd);
    k1_xp<<<2048, 256>>>(x, w_e, b_e);
    gemm_mma<0><<<dim3(40, 3, 16), 256>>>(ba, bb);
    k3_scores<<<dim3(16, 48), 512>>>();
    k4_softmax<<<48, 512>>>(PA, A_fix);
    k5_z<<<dim3(256, 16), 256>>>();
    gemm_mma<1><<<dim3(40, 2, 16), 256>>>(bd, nullptr);
    k7_bn<<<CCH, 256>>>();
    k8_final<<<20480, 256>>>(gamma, beta, out);
}

// round 10
// speedup vs baseline: 1.1445x; 1.1445x over previous
#include <cuda_runtime.h>
#include <cuda_bf16.h>
#include <cstdint>

// Problem dims
#define NB  16
#define CCH 256
#define TT  256
#define VV  25
#define VPN 20
#define SS  3
#define ICN 64
#define CT   (CCH*TT)      // 65536
#define NCOL (TT*VPN)      // 5120
#define M1 384
#define KK1 256
#define M2 256
#define KK2 768

// ---------------- scratch (device globals; no runtime allocation) -------------
__device__ float g_xp[(size_t)NB*CT*VPN];
__device__ float g_fab[(size_t)NB*M1*NCOL];
__device__ float g_spart[16*48*400];
__device__ float g_att[48*400];
__device__ float g_z[(size_t)NB*SS*CT*VPN];
__device__ float g_y[(size_t)NB*CCH*NCOL];
__device__ float g_bn[2*CCH];
// pre-split bf16 weight images, laid out exactly as the smem tiles:
// per chunk: [split hi|lo][128 rows][40 bf16 (32 k + 8 pad)]  = 10240 elems
__device__ __nv_bfloat16 g_w0[3*8*10240];    // GEMM0: 3 rowTiles x 8 chunks
__device__ __nv_bfloat16 g_w1[2*24*10240];   // GEMM1: 2 rowTiles x 24 chunks

// ---------------- weight prep: fp32 -> split bf16 images -----------------------
__global__ void prep_w0(const float* __restrict__ wa, const float* __restrict__ wb) {
    int r = blockIdx.x;          // 0..383
    int k = threadIdx.x;         // 0..255
    float v = (r < 192) ? wa[r*256 + k] : wb[(r-192)*256 + k];
    __nv_bfloat16 h = __float2bfloat16(v);
    __nv_bfloat16 l = __float2bfloat16(v - __bfloat162float(h));
    int rowTile = r >> 7, m = r & 127, ch = k >> 5, kk = k & 31;
    size_t base = (size_t)(rowTile*8 + ch) * 10240;
    g_w0[base +        m*40 + kk] = h;
    g_w0[base + 5120 + m*40 + kk] = l;
}
__global__ void prep_w1(const float* __restrict__ wd) {
    int r = blockIdx.x;          // 0..255 (output channel o)
    int k = threadIdx.x;         // 0..767 (s*256 + c)
    float v = wd[(k >> 8)*65536 + r*256 + (k & 255)];
    __nv_bfloat16 h = __float2bfloat16(v);
    __nv_bfloat16 l = __float2bfloat16(v - __bfloat162float(h));
    int rowTile = r >> 7, m = r & 127, ch = k >> 5, kk = k & 31;
    size_t base = (size_t)(rowTile*24 + ch) * 10240;
    g_w1[base +        m*40 + kk] = h;
    g_w1[base + 5120 + m*40 + kk] = l;
}

// ---------------- K1: xp = einsum('nctv,vu->nctu', x, w_e) + b_e --------------
__global__ void __launch_bounds__(256) k1_xp(const float* __restrict__ x,
                                             const float* __restrict__ w_e,
                                             const float* __restrict__ b_e) {
    __shared__ float sw[VV*VPN];
    __shared__ float sb[VPN];
    int tid = threadIdx.x;
    for (int i = tid; i < VV*VPN; i += 256) sw[i] = w_e[i];
    if (tid < VPN) sb[tid] = b_e[tid];
    __syncthreads();
    size_t row0 = ((size_t)blockIdx.x * 256 + tid) * 2;
    float xr[2][VV];
    #pragma unroll
    for (int r = 0; r < 2; r++) {
        const float* xr0 = x + (row0 + r) * VV;
        #pragma unroll
        for (int v = 0; v < VV; v++) xr[r][v] = xr0[v];
    }
    float acc[2][VPN];
    #pragma unroll
    for (int u = 0; u < VPN; u++) { float b = sb[u]; acc[0][u] = b; acc[1][u] = b; }
    #pragma unroll
    for (int v = 0; v < VV; v++) {
        float x0 = xr[0][v], x1 = xr[1][v];
        #pragma unroll
        for (int u = 0; u < VPN; u++) {
            float w = sw[v*VPN + u];
            acc[0][u] += x0 * w;
            acc[1][u] += x1 * w;
        }
    }
    #pragma unroll
    for (int r = 0; r < 2; r++) {
        float* o = &g_xp[(row0 + r) * VPN];
        #pragma unroll
        for (int q = 0; q < 5; q++)
            *(float4*)(o + q*4) = make_float4(acc[r][q*4], acc[r][q*4+1], acc[r][q*4+2], acc[r][q*4+3]);
    }
}

// ---------------- HMMA GEMM: mma.sync m16n8k16 bf16 + ldmatrix, double-buffered
__device__ __forceinline__ void mma_bf16(float* c, const uint32_t* a, const uint32_t* b) {
    asm volatile(
        "mma.sync.aligned.m16n8k16.row.col.f32.bf16.bf16.f32 "
        "{%0,%1,%2,%3}, {%4,%5,%6,%7}, {%8,%9}, {%0,%1,%2,%3};"
        : "+f"(c[0]), "+f"(c[1]), "+f"(c[2]), "+f"(c[3])
        : "r"(a[0]), "r"(a[1]), "r"(a[2]), "r"(a[3]), "r"(b[0]), "r"(b[1]));
}
__device__ __forceinline__ void ldsm_x4(uint32_t* r, uint32_t addr) {
    asm volatile("ldmatrix.sync.aligned.m8n8.x4.shared.b16 {%0,%1,%2,%3}, [%4];"
        : "=r"(r[0]), "=r"(r[1]), "=r"(r[2]), "=r"(r[3]) : "r"(addr));
}
__device__ __forceinline__ uint32_t smem_u32(const void* p) {
    uint32_t a; asm("{ .reg .u64 t; cvta.to.shared.u64 t, %1; cvt.u32.u64 %0, t; }" : "=r"(a) : "l"(p));
    return a;
}
__device__ __forceinline__ void cp16(uint32_t sdst, const void* gsrc) {
    asm volatile("cp.async.cg.shared.global [%0], [%1], 16;"
        :: "r"(sdst), "l"(__cvta_generic_to_global(gsrc)) : "memory");
}
#define CP_COMMIT() asm volatile("cp.async.commit_group;" ::: "memory")
#define CP_WAIT0()  asm volatile("cp.async.wait_group 0;" ::: "memory")

// dynamic smem: 2 buffers x [sA 20480B | sB 20480B] = 81920 bytes
#define GBUF 40960

template<int MODE>
__global__ void __launch_bounds__(256) gemm_mma(const float* __restrict__ bias0,
                                                const float* __restrict__ bias1) {
    constexpr int NCH = MODE ? 24 : 8;
    extern __shared__ __align__(16) char dynsmem[];
    uint32_t s_u = smem_u32(dynsmem);

    const __nv_bfloat16* img = MODE ? g_w1 : g_w0;
    const float* act = MODE ? g_z : g_xp;

    int tid = threadIdx.x, lane = tid & 31, wid = tid >> 5;
    int g = lane >> 2, t = lane & 3;
    int col0 = blockIdx.x * 128;
    int rowTile = blockIdx.y;
    int n = blockIdx.z;
    const float* actp = act + (size_t)n * (MODE ? 3932160 : 1310720) + col0;
    int Mw = (wid & 3) * 32, Nw = (wid >> 2) * 64;

    // ldmatrix per-thread tile-terms (bf16-element units)
    int q = lane >> 3, rr = lane & 7;
    int aTerm = ((q & 1)*8 + rr)*40 + (q >> 1)*8;
    int bTerm = ((q >> 1)*8 + rr)*40 + (q & 1)*8;

    // staging mapping: each thread owns column cS, 16 consecutive kk from kh
    int cS = tid & 127, kh = (tid >> 7) * 16;

    const __nv_bfloat16* wimg = img + (size_t)(rowTile * NCH) * 10240;

    float acc[2][8][4];
    #pragma unroll
    for (int i = 0; i < 2; i++)
        #pragma unroll
        for (int j = 0; j < 8; j++)
            #pragma unroll
            for (int qq = 0; qq < 4; qq++) acc[i][j][qq] = 0.f;

    auto stage_w = [&](int ch, int buf) {
        uint32_t dst = s_u + buf*GBUF + tid*16;
        const char* src = (const char*)(wimg + (size_t)ch * 10240) + tid*16;
        #pragma unroll
        for (int i = 0; i < 5; i++) cp16(dst + i*4096, src + i*4096);
        CP_COMMIT();
    };
    auto ldg_act = [&](int ch, int j0, float* av) {
        const float* ap = actp + (size_t)(ch*32 + kh + j0) * 5120 + cS;
        #pragma unroll
        for (int j = 0; j < 8; j++) av[j] = ap[(size_t)j * 5120];
    };
    auto sts_act = [&](int buf, int j0, const float* av) {
        // sB element [split][cS][kk]; hi at +0, lo at +10240 bytes
        char* base = dynsmem + buf*GBUF + 20480 + (cS*40 + kh + j0)*2;
        #pragma unroll
        for (int j = 0; j < 8; j += 2) {
            float f0 = av[j], f1 = av[j+1];
            __nv_bfloat16 h0 = __float2bfloat16(f0), h1 = __float2bfloat16(f1);
            __nv_bfloat16 l0 = __float2bfloat16(f0 - __bfloat162float(h0));
            __nv_bfloat16 l1 = __float2bfloat16(f1 - __bfloat162float(h1));
            uint32_t hw = (uint32_t)__bfloat16_as_ushort(h0) | ((uint32_t)__bfloat16_as_ushort(h1) << 16);
            uint32_t lw = (uint32_t)__bfloat16_as_ushort(l0) | ((uint32_t)__bfloat16_as_ushort(l1) << 16);
            *(uint32_t*)(base + j*2)          = hw;
            *(uint32_t*)(base + 10240 + j*2)  = lw;
        }
    };
    auto compute_half = [&](int buf, int k0) {
        uint32_t aB = s_u + buf*GBUF;
        uint32_t bB = aB + 20480;
        uint32_t ah[2][4], al[2][4], bh[8][2], bl[8][2];
        #pragma unroll
        for (int mf = 0; mf < 2; mf++) {
            uint32_t base = aB + (uint32_t)(((Mw + mf*16)*40 + k0 + aTerm) * 2);
            ldsm_x4(ah[mf], base);
            ldsm_x4(al[mf], base + 10240u);
        }
        #pragma unroll
        for (int pf = 0; pf < 4; pf++) {
            uint32_t base = bB + (uint32_t)(((Nw + pf*16)*40 + k0 + bTerm) * 2);
            ldsm_x4(&bh[2*pf][0], base);
            ldsm_x4(&bl[2*pf][0], base + 10240u);
        }
        #pragma unroll
        for (int mf = 0; mf < 2; mf++)
            #pragma unroll
            for (int nf = 0; nf < 8; nf++) {
                mma_bf16(acc[mf][nf], ah[mf], bh[nf]);   // hi*hi
                mma_bf16(acc[mf][nf], ah[mf], bl[nf]);   // hi*lo
                mma_bf16(acc[mf][nf], al[mf], bh[nf]);   // lo*hi
            }
    };

    // prologue: fill buffer 0
    stage_w(0, 0);
    {
        float av[8];
        ldg_act(0, 0, av); sts_act(0, 0, av);
        ldg_act(0, 8, av); sts_act(0, 8, av);
    }
    CP_WAIT0();
    __syncthreads();

    for (int ch = 0; ch < NCH; ch++) {
        int bcur = ch & 1, bnext = bcur ^ 1;
        bool more = (ch + 1 < NCH);
        float av[8];
        if (more) { stage_w(ch+1, bnext); ldg_act(ch+1, 0, av); }
        compute_half(bcur, 0);
        if (more) { sts_act(bnext, 0, av); ldg_act(ch+1, 8, av); }
        compute_half(bcur, 16);
        if (more) { sts_act(bnext, 8, av); CP_WAIT0(); }
        __syncthreads();
    }

    // epilogue: direct global stores (+bias), float2 per c-pair
    float* outb = (MODE ? g_y : g_fab) + (size_t)n * (MODE ? 1310720 : 1966080);
    #pragma unroll
    for (int mf = 0; mf < 2; mf++) {
        int r = rowTile*128 + Mw + mf*16 + g;
        float bv0, bv1;
        if (MODE) {
            bv0 = bias0[r]   + bias0[256 + r]   + bias0[512 + r];
            bv1 = bias0[r+8] + bias0[256 + r+8] + bias0[512 + r+8];
        } else {
            bv0 = (r   < 192) ? bias0[r]   : bias1[r   - 192];
            bv1 = (r+8 < 192) ? bias0[r+8] : bias1[r+8 - 192];
        }
        #pragma unroll
        for (int nf = 0; nf < 8; nf++) {
            int col = col0 + Nw + nf*8 + 2*t;
            float* o = outb + (size_t)r * 5120 + col;
            *(float2*)o              = make_float2(acc[mf][nf][0] + bv0, acc[mf][nf][1] + bv0);
            *(float2*)(o + 8*5120)   = make_float2(acc[mf][nf][2] + bv1, acc[mf][nf][3] + bv1);
        }
    }
}

// ---------------- K3: scores partials ------------------------------------------
__global__ void __launch_bounds__(512) k3_scores() {
    __shared__ float sfa[8][320];
    __shared__ float sfb[8][320];
    int tid = threadIdx.x;
    int tc = blockIdx.x;
    int ns = blockIdx.y;
    int n = ns / 3, s = ns % 3;
    const float* faB = g_fab + (size_t)n*M1*NCOL + (size_t)(s*64)*NCOL + tc*320;
    const float* fbB = faB + (size_t)192*NCOL;
    float acc = 0.f;
    int v = tid / 20, u = tid % 20;
    for (int ib = 0; ib < 64; ib += 8) {
        for (int idx = tid; idx < 2560; idx += 512) {
            int ii = idx / 320, jj = idx % 320;
            sfa[ii][jj] = faB[(size_t)(ib+ii)*NCOL + jj];
            sfb[ii][jj] = fbB[(size_t)(ib+ii)*NCOL + jj];
        }
        __syncthreads();
        if (tid < 400) {
            #pragma unroll
            for (int ii = 0; ii < 8; ii++)
                #pragma unroll
                for (int t2 = 0; t2 < 16; t2++)
                    acc += sfa[ii][t2*20 + v] * sfb[ii][t2*20 + u];
        }
        __syncthreads();
    }
    if (tid < 400)
        g_spart[(tc*48 + ns)*400 + tid] = acc * (1.0f/16384.0f);
}

// ---------------- K4: reduce + softmax over v + (A_fix+PA) ---------------------
__global__ void __launch_bounds__(512) k4_softmax(const float* __restrict__ PA,
                                                  const float* __restrict__ A_fix) {
    __shared__ float ssc[400];
    int tid = threadIdx.x;
    int ns = blockIdx.x;
    int s = ns % 3;
    if (tid < 400) {
        float a = 0.f;
        #pragma unroll
        for (int tc = 0; tc < 16; tc++) a += g_spart[(tc*48 + ns)*400 + tid];
        ssc[tid] = a;
    }
    __syncthreads();
    if (tid < 20) {
        int u = tid;
        float mx = -1e30f;
        #pragma unroll
        for (int v = 0; v < 20; v++) mx = fmaxf(mx, ssc[v*20 + u]);
        float e[20];
        float sum = 0.f;
        #pragma unroll
        for (int v = 0; v < 20; v++) { e[v] = expf(ssc[v*20 + u] - mx); sum += e[v]; }
        float inv = 1.0f / sum;
        #pragma unroll
        for (int v = 0; v < 20; v++) {
            int ai = (s*20 + v)*20 + u;
            g_att[ns*400 + v*20 + u] = e[v]*inv + A_fix[ai] + PA[ai];
        }
    }
}

// ---------------- K5: z for all 3 subsets from one xp read ---------------------
__global__ void __launch_bounds__(256) k5_z() {
    __shared__ float satt[3*400];
    int tid = threadIdx.x;
    int n = blockIdx.y;
    for (int i = tid; i < 3*400; i += 256) satt[i] = g_att[n*1200 + i];
    __syncthreads();
    size_t row = (size_t)blockIdx.x * 256 + tid;
    const float* xr0 = &g_xp[((size_t)n*CT + row)*VPN];
    float xr[20];
    #pragma unroll
    for (int q = 0; q < 5; q++)
        *(float4*)&xr[q*4] = *(const float4*)(xr0 + q*4);
    #pragma unroll
    for (int s = 0; s < 3; s++) {
        float acc[20];
        #pragma unroll
        for (int u = 0; u < 20; u++) acc[u] = 0.f;
        #pragma unroll
        for (int v = 0; v < 20; v++) {
            float x0 = xr[v];
            #pragma unroll
            for (int u = 0; u < 20; u++)
                acc[u] += x0 * satt[s*400 + v*20 + u];
        }
        float* zp = &g_z[(((size_t)n*3 + s)*CT + row)*VPN];
        #pragma unroll
        for (int q = 0; q < 5; q++)
            *(float4*)(zp + q*4) = make_float4(acc[q*4], acc[q*4+1], acc[q*4+2], acc[q*4+3]);
    }
}

// ---------------- K7: BN statistics ---------------------------------------------
__global__ void __launch_bounds__(256) k7_bn() {
    __shared__ double ssum[256];
    __shared__ double ssq[256];
    int o = blockIdx.x, tid = threadIdx.x;
    double s = 0.0, q = 0.0;
    for (int n = 0; n < NB; n++) {
        const float* yp = &g_y[((size_t)n*CCH + o)*NCOL];
        for (int j = tid; j < NCOL; j += 256) { double v = yp[j]; s += v; q += v*v; }
    }
    ssum[tid] = s; ssq[tid] = q;
    __syncthreads();
    for (int st = 128; st > 0; st >>= 1) {
        if (tid < st) { ssum[tid] += ssum[tid+st]; ssq[tid] += ssq[tid+st]; }
        __syncthreads();
    }
    if (tid == 0) {
        double cnt  = (double)NB * NCOL;
        double mean = ssum[0] / cnt;
        double var  = ssq[0] / cnt - mean*mean;
        g_bn[o]       = (float)mean;
        g_bn[256 + o] = (float)(1.0 / sqrt(var + 1e-5));
    }
}

// ---------------- K8: out = relu(BN(y)*gamma+beta + xp) -------------------------
__global__ void __launch_bounds__(256) k8_final(const float* __restrict__ gamma,
                                                const float* __restrict__ beta,
                                                float* __restrict__ out) {
    size_t idx = ((size_t)blockIdx.x * 256 + threadIdx.x) * 4;
    int o = (int)((idx / NCOL) % CCH);
    float rstd = g_bn[256 + o];
    float g = gamma[o] * rstd;
    float b = beta[o] - g_bn[o] * g;
    float4 y  = *(const float4*)&g_y[idx];
    float4 xp = *(const float4*)&g_xp[idx];
    float4 r;
    r.x = fmaxf(y.x*g + b + xp.x, 0.f);
    r.y = fmaxf(y.y*g + b + xp.y, 0.f);
    r.z = fmaxf(y.z*g + b + xp.z, 0.f);
    r.w = fmaxf(y.w*g + b + xp.w, 0.f);
    *(float4*)&out[idx] = r;
}

// ---------------- launch ---------------------------------------------------------
extern "C" void kernel_launch(void* const* d_in, const int* in_sizes, int n_in,
                              void* d_out, int out_size) {
    const float* x     = (const float*)d_in[0];
    const float* PA    = (const float*)d_in[1];
    const float* A_fix = (const float*)d_in[2];
    const float* w_e   = (const float*)d_in[3];
    const float* b_e   = (const float*)d_in[4];
    const float* wa    = (const float*)d_in[5];
    const float* ba    = (const float*)d_in[6];
    const float* wb    = (const float*)d_in[7];
    const float* bb    = (const float*)d_in[8];
    const float* wd    = (const float*)d_in[9];
    const float* bd    = (const float*)d_in[10];
    const float* gamma = (const float*)d_in[11];
    const float* beta  = (const float*)d_in[12];
    float* out = (float*)d_out;

    // allow 80KB dynamic smem for the double-buffered GEMMs (host-side, capture-safe)
    cudaFuncSetAttribute(gemm_mma<0>, cudaFuncAttributeMaxDynamicSharedMemorySize, 2*GBUF);
    cudaFuncSetAttribute(gemm_mma<1>, cudaFuncAttributeMaxDynamicSharedMemorySize, 2*GBUF);

    prep_w0<<<384, 256>>>(wa, wb);
    prep_w1<<<256, 768>>>(wd);
    k1_xp<<<2048, 256>>>(x, w_e, b_e);
    gemm_mma<0><<<dim3(40, 3, 16), 256, 2*GBUF>>>(ba, bb);
    k3_scores<<<dim3(16, 48), 512>>>();
    k4_softmax<<<48, 512>>>(PA, A_fix);
    k5_z<<<dim3(256, 16), 256>>>();
    gemm_mma<1><<<dim3(40, 2, 16), 256, 2*GBUF>>>(bd, nullptr);
    k7_bn<<<CCH, 256>>>();
    k8_final<<<20480, 256>>>(gamma, beta, out);
}

// round 11
// speedup vs baseline: 1.3609x; 1.1891x over previous
#include <cuda_runtime.h>
#include <cuda_bf16.h>
#include <cstdint>

// Problem dims
#define NB  16
#define CCH 256
#define TT  256
#define VV  25
#define VPN 20
#define SS  3
#define ICN 64
#define CT   (CCH*TT)      // 65536
#define NCOL (TT*VPN)      // 5120
#define M1 384
#define KK1 256
#define M2 256
#define KK2 768

// ---------------- scratch (device globals; no runtime allocation) -------------
__device__ float g_xp[(size_t)NB*CT*VPN];
__device__ float g_fab[(size_t)NB*M1*NCOL];
__device__ float g_spart[16*48*400];
__device__ float g_att[48*400];
__device__ float g_z[(size_t)NB*SS*CT*VPN];
__device__ float g_y[(size_t)NB*CCH*NCOL];
__device__ float g_bn[2*CCH];
// pre-split bf16 weight images, laid out exactly as the smem tiles:
// per chunk: [split hi|lo][128 rows][40 bf16 (32 k + 8 pad)]  = 10240 elems
__device__ __nv_bfloat16 g_w0[3*8*10240];    // GEMM0: 3 rowTiles x 8 chunks
__device__ __nv_bfloat16 g_w1[2*24*10240];   // GEMM1: 2 rowTiles x 24 chunks

// ---------------- weight prep: fp32 -> split bf16 images -----------------------
__global__ void prep_w0(const float* __restrict__ wa, const float* __restrict__ wb) {
    int r = blockIdx.x;          // 0..383
    int k = threadIdx.x;         // 0..255
    float v = (r < 192) ? wa[r*256 + k] : wb[(r-192)*256 + k];
    __nv_bfloat16 h = __float2bfloat16(v);
    __nv_bfloat16 l = __float2bfloat16(v - __bfloat162float(h));
    int rowTile = r >> 7, m = r & 127, ch = k >> 5, kk = k & 31;
    size_t base = (size_t)(rowTile*8 + ch) * 10240;
    g_w0[base +        m*40 + kk] = h;
    g_w0[base + 5120 + m*40 + kk] = l;
}
__global__ void prep_w1(const float* __restrict__ wd) {
    int r = blockIdx.x;          // 0..255 (output channel o)
    int k = threadIdx.x;         // 0..767 (s*256 + c)
    float v = wd[(k >> 8)*65536 + r*256 + (k & 255)];
    __nv_bfloat16 h = __float2bfloat16(v);
    __nv_bfloat16 l = __float2bfloat16(v - __bfloat162float(h));
    int rowTile = r >> 7, m = r & 127, ch = k >> 5, kk = k & 31;
    size_t base = (size_t)(rowTile*24 + ch) * 10240;
    g_w1[base +        m*40 + kk] = h;
    g_w1[base + 5120 + m*40 + kk] = l;
}

// ---------------- K1: xp = einsum('nctv,vu->nctu', x, w_e) + b_e --------------
__global__ void __launch_bounds__(256) k1_xp(const float* __restrict__ x,
                                             const float* __restrict__ w_e,
                                             const float* __restrict__ b_e) {
    __shared__ float sw[VV*VPN];
    __shared__ float sb[VPN];
    int tid = threadIdx.x;
    for (int i = tid; i < VV*VPN; i += 256) sw[i] = w_e[i];
    if (tid < VPN) sb[tid] = b_e[tid];
    __syncthreads();
    size_t row0 = ((size_t)blockIdx.x * 256 + tid) * 2;
    float xr[2][VV];
    #pragma unroll
    for (int r = 0; r < 2; r++) {
        const float* xr0 = x + (row0 + r) * VV;
        #pragma unroll
        for (int v = 0; v < VV; v++) xr[r][v] = xr0[v];
    }
    float acc[2][VPN];
    #pragma unroll
    for (int u = 0; u < VPN; u++) { float b = sb[u]; acc[0][u] = b; acc[1][u] = b; }
    #pragma unroll
    for (int v = 0; v < VV; v++) {
        float x0 = xr[0][v], x1 = xr[1][v];
        #pragma unroll
        for (int u = 0; u < VPN; u++) {
            float w = sw[v*VPN + u];
            acc[0][u] += x0 * w;
            acc[1][u] += x1 * w;
        }
    }
    #pragma unroll
    for (int r = 0; r < 2; r++) {
        float* o = &g_xp[(row0 + r) * VPN];
        #pragma unroll
        for (int q = 0; q < 5; q++)
            *(float4*)(o + q*4) = make_float4(acc[r][q*4], acc[r][q*4+1], acc[r][q*4+2], acc[r][q*4+3]);
    }
}

// ---------------- HMMA GEMM: mma.sync m16n8k16 bf16 + ldmatrix, double-buffered
__device__ __forceinline__ void mma_bf16(float* c, const uint32_t* a, const uint32_t* b) {
    asm volatile(
        "mma.sync.aligned.m16n8k16.row.col.f32.bf16.bf16.f32 "
        "{%0,%1,%2,%3}, {%4,%5,%6,%7}, {%8,%9}, {%0,%1,%2,%3};"
        : "+f"(c[0]), "+f"(c[1]), "+f"(c[2]), "+f"(c[3])
        : "r"(a[0]), "r"(a[1]), "r"(a[2]), "r"(a[3]), "r"(b[0]), "r"(b[1]));
}
__device__ __forceinline__ void ldsm_x4(uint32_t* r, uint32_t addr) {
    asm volatile("ldmatrix.sync.aligned.m8n8.x4.shared.b16 {%0,%1,%2,%3}, [%4];"
        : "=r"(r[0]), "=r"(r[1]), "=r"(r[2]), "=r"(r[3]) : "r"(addr));
}
__device__ __forceinline__ uint32_t smem_u32(const void* p) {
    uint32_t a; asm("{ .reg .u64 t; cvta.to.shared.u64 t, %1; cvt.u32.u64 %0, t; }" : "=r"(a) : "l"(p));
    return a;
}
__device__ __forceinline__ void cp16(uint32_t sdst, const void* gsrc) {
    asm volatile("cp.async.cg.shared.global [%0], [%1], 16;"
        :: "r"(sdst), "l"(__cvta_generic_to_global(gsrc)) : "memory");
}
#define CP_COMMIT() asm volatile("cp.async.commit_group;" ::: "memory")
#define CP_WAIT0()  asm volatile("cp.async.wait_group 0;" ::: "memory")

// dynamic smem: 2 buffers x [sA 20480B | sB 20480B] = 81920 bytes
#define GBUF 40960

template<int MODE>
__global__ void __launch_bounds__(256, 2) gemm_mma(const float* __restrict__ bias0,
                                                   const float* __restrict__ bias1) {
    constexpr int NCH = MODE ? 24 : 8;
    extern __shared__ __align__(16) char dynsmem[];
    uint32_t s_u = smem_u32(dynsmem);

    const __nv_bfloat16* img = MODE ? g_w1 : g_w0;
    const float* act = MODE ? g_z : g_xp;

    int tid = threadIdx.x, lane = tid & 31, wid = tid >> 5;
    int g = lane >> 2, t = lane & 3;
    int col0 = blockIdx.x * 128;
    int rowTile = blockIdx.y;
    int n = blockIdx.z;
    const float* actp = act + (size_t)n * (MODE ? 3932160 : 1310720) + col0;
    int Mw = (wid & 3) * 32, Nw = (wid >> 2) * 64;

    // ldmatrix per-thread tile-terms (bf16-element units)
    int q = lane >> 3, rr = lane & 7;
    int aTerm = ((q & 1)*8 + rr)*40 + (q >> 1)*8;
    int bTerm = ((q >> 1)*8 + rr)*40 + (q & 1)*8;

    // staging mapping: each thread owns column cS, 16 consecutive kk from kh
    int cS = tid & 127, kh = (tid >> 7) * 16;

    const __nv_bfloat16* wimg = img + (size_t)(rowTile * NCH) * 10240;

    float acc[2][8][4];
    #pragma unroll
    for (int i = 0; i < 2; i++)
        #pragma unroll
        for (int j = 0; j < 8; j++)
            #pragma unroll
            for (int qq = 0; qq < 4; qq++) acc[i][j][qq] = 0.f;

    auto stage_w = [&](int ch, int buf) {
        uint32_t dst = s_u + buf*GBUF + tid*16;
        const char* src = (const char*)(wimg + (size_t)ch * 10240) + tid*16;
        #pragma unroll
        for (int i = 0; i < 5; i++) cp16(dst + i*4096, src + i*4096);
        CP_COMMIT();
    };
    auto ldg_act = [&](int ch, int j0, float* av) {
        const float* ap = actp + (size_t)(ch*32 + kh + j0) * 5120 + cS;
        #pragma unroll
        for (int j = 0; j < 8; j++) av[j] = ap[(size_t)j * 5120];
    };
    auto sts_act = [&](int buf, int j0, const float* av) {
        // sB element [split][cS][kk]; hi at +0, lo at +10240 bytes
        char* base = dynsmem + buf*GBUF + 20480 + (cS*40 + kh + j0)*2;
        #pragma unroll
        for (int j = 0; j < 8; j += 2) {
            float f0 = av[j], f1 = av[j+1];
            __nv_bfloat16 h0 = __float2bfloat16(f0), h1 = __float2bfloat16(f1);
            __nv_bfloat16 l0 = __float2bfloat16(f0 - __bfloat162float(h0));
            __nv_bfloat16 l1 = __float2bfloat16(f1 - __bfloat162float(h1));
            uint32_t hw = (uint32_t)__bfloat16_as_ushort(h0) | ((uint32_t)__bfloat16_as_ushort(h1) << 16);
            uint32_t lw = (uint32_t)__bfloat16_as_ushort(l0) | ((uint32_t)__bfloat16_as_ushort(l1) << 16);
            *(uint32_t*)(base + j*2)          = hw;
            *(uint32_t*)(base + 10240 + j*2)  = lw;
        }
    };
    // restructured: B fragments loaded per pf-pair -> 24 live fragment regs, fits 128-reg cap
    auto compute_half = [&](int buf, int k0) {
        uint32_t aB = s_u + buf*GBUF;
        uint32_t bB = aB + 20480;
        uint32_t ah[2][4], al[2][4];
        #pragma unroll
        for (int mf = 0; mf < 2; mf++) {
            uint32_t base = aB + (uint32_t)(((Mw + mf*16)*40 + k0 + aTerm) * 2);
            ldsm_x4(ah[mf], base);
            ldsm_x4(al[mf], base + 10240u);
        }
        #pragma unroll
        for (int pf = 0; pf < 4; pf++) {
            uint32_t b4h[4], b4l[4];
            uint32_t base = bB + (uint32_t)(((Nw + pf*16)*40 + k0 + bTerm) * 2);
            ldsm_x4(b4h, base);
            ldsm_x4(b4l, base + 10240u);
            #pragma unroll
            for (int mf = 0; mf < 2; mf++) {
                // nf = 2*pf   : fragments b4{h,l}[0..1]
                mma_bf16(acc[mf][2*pf],   ah[mf], b4h);       // hi*hi
                mma_bf16(acc[mf][2*pf],   ah[mf], b4l);       // hi*lo
                mma_bf16(acc[mf][2*pf],   al[mf], b4h);       // lo*hi
                // nf = 2*pf+1 : fragments b4{h,l}[2..3]
                mma_bf16(acc[mf][2*pf+1], ah[mf], b4h + 2);
                mma_bf16(acc[mf][2*pf+1], ah[mf], b4l + 2);
                mma_bf16(acc[mf][2*pf+1], al[mf], b4h + 2);
            }
        }
    };

    // prologue: fill buffer 0
    stage_w(0, 0);
    {
        float av[8];
        ldg_act(0, 0, av); sts_act(0, 0, av);
        ldg_act(0, 8, av); sts_act(0, 8, av);
    }
    CP_WAIT0();
    __syncthreads();

    for (int ch = 0; ch < NCH; ch++) {
        int bcur = ch & 1, bnext = bcur ^ 1;
        bool more = (ch + 1 < NCH);
        float av[8];
        if (more) { stage_w(ch+1, bnext); ldg_act(ch+1, 0, av); }
        compute_half(bcur, 0);
        if (more) { sts_act(bnext, 0, av); ldg_act(ch+1, 8, av); }
        compute_half(bcur, 16);
        if (more) { sts_act(bnext, 8, av); CP_WAIT0(); }
        __syncthreads();
    }

    // epilogue: direct global stores (+bias), float2 per c-pair
    float* outb = (MODE ? g_y : g_fab) + (size_t)n * (MODE ? 1310720 : 1966080);
    #pragma unroll
    for (int mf = 0; mf < 2; mf++) {
        int r = rowTile*128 + Mw + mf*16 + g;
        float bv0, bv1;
        if (MODE) {
            bv0 = bias0[r]   + bias0[256 + r]   + bias0[512 + r];
            bv1 = bias0[r+8] + bias0[256 + r+8] + bias0[512 + r+8];
        } else {
            bv0 = (r   < 192) ? bias0[r]   : bias1[r   - 192];
            bv1 = (r+8 < 192) ? bias0[r+8] : bias1[r+8 - 192];
        }
        #pragma unroll
        for (int nf = 0; nf < 8; nf++) {
            int col = col0 + Nw + nf*8 + 2*t;
            float* o = outb + (size_t)r * 5120 + col;
            *(float2*)o              = make_float2(acc[mf][nf][0] + bv0, acc[mf][nf][1] + bv0);
            *(float2*)(o + 8*5120)   = make_float2(acc[mf][nf][2] + bv1, acc[mf][nf][3] + bv1);
        }
    }
}

// ---------------- K3: scores partials ------------------------------------------
__global__ void __launch_bounds__(512) k3_scores() {
    __shared__ float sfa[8][320];
    __shared__ float sfb[8][320];
    int tid = threadIdx.x;
    int tc = blockIdx.x;
    int ns = blockIdx.y;
    int n = ns / 3, s = ns % 3;
    const float* faB = g_fab + (size_t)n*M1*NCOL + (size_t)(s*64)*NCOL + tc*320;
    const float* fbB = faB + (size_t)192*NCOL;
    float acc = 0.f;
    int v = tid / 20, u = tid % 20;
    for (int ib = 0; ib < 64; ib += 8) {
        for (int idx = tid; idx < 2560; idx += 512) {
            int ii = idx / 320, jj = idx % 320;
            sfa[ii][jj] = faB[(size_t)(ib+ii)*NCOL + jj];
            sfb[ii][jj] = fbB[(size_t)(ib+ii)*NCOL + jj];
        }
        __syncthreads();
        if (tid < 400) {
            #pragma unroll
            for (int ii = 0; ii < 8; ii++)
                #pragma unroll
                for (int t2 = 0; t2 < 16; t2++)
                    acc += sfa[ii][t2*20 + v] * sfb[ii][t2*20 + u];
        }
        __syncthreads();
    }
    if (tid < 400)
        g_spart[(tc*48 + ns)*400 + tid] = acc * (1.0f/16384.0f);
}

// ---------------- K4: reduce + softmax over v + (A_fix+PA) ---------------------
__global__ void __launch_bounds__(512) k4_softmax(const float* __restrict__ PA,
                                                  const float* __restrict__ A_fix) {
    __shared__ float ssc[400];
    int tid = threadIdx.x;
    int ns = blockIdx.x;
    int s = ns % 3;
    if (tid < 400) {
        float a = 0.f;
        #pragma unroll
        for (int tc = 0; tc < 16; tc++) a += g_spart[(tc*48 + ns)*400 + tid];
        ssc[tid] = a;
    }
    __syncthreads();
    if (tid < 20) {
        int u = tid;
        float mx = -1e30f;
        #pragma unroll
        for (int v = 0; v < 20; v++) mx = fmaxf(mx, ssc[v*20 + u]);
        float e[20];
        float sum = 0.f;
        #pragma unroll
        for (int v = 0; v < 20; v++) { e[v] = expf(ssc[v*20 + u] - mx); sum += e[v]; }
        float inv = 1.0f / sum;
        #pragma unroll
        for (int v = 0; v < 20; v++) {
            int ai = (s*20 + v)*20 + u;
            g_att[ns*400 + v*20 + u] = e[v]*inv + A_fix[ai] + PA[ai];
        }
    }
}

// ---------------- K5: z for all 3 subsets from one xp read ---------------------
__global__ void __launch_bounds__(256) k5_z() {
    __shared__ float satt[3*400];
    int tid = threadIdx.x;
    int n = blockIdx.y;
    for (int i = tid; i < 3*400; i += 256) satt[i] = g_att[n*1200 + i];
    __syncthreads();
    size_t row = (size_t)blockIdx.x * 256 + tid;
    const float* xr0 = &g_xp[((size_t)n*CT + row)*VPN];
    float xr[20];
    #pragma unroll
    for (int q = 0; q < 5; q++)
        *(float4*)&xr[q*4] = *(const float4*)(xr0 + q*4);
    #pragma unroll
    for (int s = 0; s < 3; s++) {
        float acc[20];
        #pragma unroll
        for (int u = 0; u < 20; u++) acc[u] = 0.f;
        #pragma unroll
        for (int v = 0; v < 20; v++) {
            float x0 = xr[v];
            #pragma unroll
            for (int u = 0; u < 20; u++)
                acc[u] += x0 * satt[s*400 + v*20 + u];
        }
        float* zp = &g_z[(((size_t)n*3 + s)*CT + row)*VPN];
        #pragma unroll
        for (int q = 0; q < 5; q++)
            *(float4*)(zp + q*4) = make_float4(acc[q*4], acc[q*4+1], acc[q*4+2], acc[q*4+3]);
    }
}

// ---------------- K7: BN statistics ---------------------------------------------
__global__ void __launch_bounds__(256) k7_bn() {
    __shared__ double ssum[256];
    __shared__ double ssq[256];
    int o = blockIdx.x, tid = threadIdx.x;
    double s = 0.0, q = 0.0;
    for (int n = 0; n < NB; n++) {
        const float* yp = &g_y[((size_t)n*CCH + o)*NCOL];
        for (int j = tid; j < NCOL; j += 256) { double v = yp[j]; s += v; q += v*v; }
    }
    ssum[tid] = s; ssq[tid] = q;
    __syncthreads();
    for (int st = 128; st > 0; st >>= 1) {
        if (tid < st) { ssum[tid] += ssum[tid+st]; ssq[tid] += ssq[tid+st]; }
        __syncthreads();
    }
    if (tid == 0) {
        double cnt  = (double)NB * NCOL;
        double mean = ssum[0] / cnt;
        double var  = ssq[0] / cnt - mean*mean;
        g_bn[o]       = (float)mean;
        g_bn[256 + o] = (float)(1.0 / sqrt(var + 1e-5));
    }
}

// ---------------- K8: out = relu(BN(y)*gamma+beta + xp) -------------------------
__global__ void __launch_bounds__(256) k8_final(const float* __restrict__ gamma,
                                                const float* __restrict__ beta,
                                                float* __restrict__ out) {
    size_t idx = ((size_t)blockIdx.x * 256 + threadIdx.x) * 4;
    int o = (int)((idx / NCOL) % CCH);
    float rstd = g_bn[256 + o];
    float g = gamma[o] * rstd;
    float b = beta[o] - g_bn[o] * g;
    float4 y  = *(const float4*)&g_y[idx];
    float4 xp = *(const float4*)&g_xp[idx];
    float4 r;
    r.x = fmaxf(y.x*g + b + xp.x, 0.f);
    r.y = fmaxf(y.y*g + b + xp.y, 0.f);
    r.z = fmaxf(y.z*g + b + xp.z, 0.f);
    r.w = fmaxf(y.w*g + b + xp.w, 0.f);
    *(float4*)&out[idx] = r;
}

// ---------------- launch ---------------------------------------------------------
extern "C" void kernel_launch(void* const* d_in, const int* in_sizes, int n_in,
                              void* d_out, int out_size) {
    const float* x     = (const float*)d_in[0];
    const float* PA    = (const float*)d_in[1];
    const float* A_fix = (const float*)d_in[2];
    const float* w_e   = (const float*)d_in[3];
    const float* b_e   = (const float*)d_in[4];
    const float* wa    = (const float*)d_in[5];
    const float* ba    = (const float*)d_in[6];
    const float* wb    = (const float*)d_in[7];
    const float* bb    = (const float*)d_in[8];
    const float* wd    = (const float*)d_in[9];
    const float* bd    = (const float*)d_in[10];
    const float* gamma = (const float*)d_in[11];
    const float* beta  = (const float*)d_in[12];
    float* out = (float*)d_out;

    // allow 80KB dynamic smem for the double-buffered GEMMs (host-side, capture-safe)
    cudaFuncSetAttribute(gemm_mma<0>, cudaFuncAttributeMaxDynamicSharedMemorySize, 2*GBUF);
    cudaFuncSetAttribute(gemm_mma<1>, cudaFuncAttributeMaxDynamicSharedMemorySize, 2*GBUF);

    prep_w0<<<384, 256>>>(wa, wb);
    prep_w1<<<256, 768>>>(wd);
    k1_xp<<<2048, 256>>>(x, w_e, b_e);
    gemm_mma<0><<<dim3(40, 3, 16), 256, 2*GBUF>>>(ba, bb);
    k3_scores<<<dim3(16, 48), 512>>>();
    k4_softmax<<<48, 512>>>(PA, A_fix);
    k5_z<<<dim3(256, 16), 256>>>();
    gemm_mma<1><<<dim3(40, 2, 16), 256, 2*GBUF>>>(bd, nullptr);
    k7_bn<<<CCH, 256>>>();
    k8_final<<<20480, 256>>>(gamma, beta, out);
}